// round 2
// baseline (speedup 1.0000x reference)
#include <cuda_runtime.h>

// x:   [B, N, 128] f32  -> viewed as [B*N, 32] float4 (32 float4 per point)
// R:   [B, N, 2, 2] f32 -> viewed as [B*N] float4 (r00, r01, r10, r11)
// y0 = r00*x0 + r01*x1 ; y1 = r10*x0 + r11*x1 for each consecutive pair.
//
// Each thread handles 4 consecutive float4 (64B) from ONE point:
//   tid*4 .. tid*4+3 all lie in the same 32-float4 point (4 | 32, aligned).
// So one R load serves 4 output float4s. Streaming hints on x/out.

__device__ __forceinline__ float4 rot4(float4 r, float4 v) {
    float4 o;
    o.x = fmaf(r.x, v.x, r.y * v.y);
    o.y = fmaf(r.z, v.x, r.w * v.y);
    o.z = fmaf(r.x, v.z, r.y * v.w);
    o.w = fmaf(r.z, v.z, r.w * v.w);
    return o;
}

__global__ __launch_bounds__(256) void rot2_kernel(
    const float4* __restrict__ x,
    const float4* __restrict__ R,
    float4* __restrict__ out,
    int n4)
{
    int t = blockIdx.x * blockDim.x + threadIdx.x;
    int i = t << 2;                     // first of 4 consecutive float4
    if (i >= n4) return;

    int point = i >> 5;                 // 32 float4 per point
    float4 r = __ldg(&R[point]);        // cached, reused by 8 threads

    // Front-batch 4 independent streaming loads (MLP)
    float4 v0 = __ldcs(&x[i + 0]);
    float4 v1 = __ldcs(&x[i + 1]);
    float4 v2 = __ldcs(&x[i + 2]);
    float4 v3 = __ldcs(&x[i + 3]);

    __stcs(&out[i + 0], rot4(r, v0));
    __stcs(&out[i + 1], rot4(r, v1));
    __stcs(&out[i + 2], rot4(r, v2));
    __stcs(&out[i + 3], rot4(r, v3));
}

extern "C" void kernel_launch(void* const* d_in, const int* in_sizes, int n_in,
                              void* d_out, int out_size)
{
    const float4* x = (const float4*)d_in[0];
    const float4* R = (const float4*)d_in[1];
    float4* out = (float4*)d_out;

    int n4 = out_size / 4;              // total float4 count (8,388,608)
    int threads = 256;
    int f4_per_block = threads * 4;
    int blocks = (n4 + f4_per_block - 1) / f4_per_block;
    rot2_kernel<<<blocks, threads>>>(x, R, out, n4);
}